// round 13
// baseline (speedup 1.0000x reference)
#include <cuda_runtime.h>
#include <cstdint>

#define N_RES 768
#define C_M   256
#define C_Z   128
#define NO_BINS 15
#define EPS 1e-5f

#define ROWS_PER_WARP 16
#define NZBLOCKS ((N_RES * N_RES) / ROWS_PER_WARP / 8)   // 4608
#define NMBLOCKS (N_RES / 8)                              // 96

// Squared bin edges (3.25 + 1.25k)^2 — exactly representable in fp32.
#define E0  10.5625f
#define E1  20.25f
#define E2  33.0625f
#define E3  49.0f
#define E4  68.0625f
#define E5  90.25f
#define E6  115.5625f
#define E7  144.0f
#define E8  175.5625f
#define E9  210.25f
#define E10 248.0625f
#define E11 289.0f
#define E12 333.0625f
#define E13 380.25f
#define E14 430.5625f

__global__ __launch_bounds__(256, 5)
void fused_kernel(const float* __restrict__ z,
                  const float* __restrict__ x,
                  const float* __restrict__ g_z,
                  const float* __restrict__ m,
                  const float* __restrict__ g_m,
                  const float* __restrict__ be_m,
                  const float* __restrict__ w_lin,   // [C_Z, NO_BINS]
                  const float* __restrict__ b_lin,   // [C_Z]
                  const float* __restrict__ be_z,    // [C_Z]
                  float* __restrict__ out_m,
                  float* __restrict__ out_z)
{
    const unsigned lane = threadIdx.x & 31u;

    // =====================================================================
    // m-layernorm path: blocks [NZBLOCKS, NZBLOCKS + NMBLOCKS)
    // =====================================================================
    if (blockIdx.x >= NZBLOCKS) {
        const unsigned row = (blockIdx.x - NZBLOCKS) * 8u + (threadIdx.x >> 5);

        const float4* mrow = reinterpret_cast<const float4*>(m + (size_t)row * C_M);
        float4 a = mrow[lane];
        float4 b = mrow[lane + 32];

        float s  = a.x + a.y + a.z + a.w + b.x + b.y + b.z + b.w;
        float sq = a.x*a.x + a.y*a.y + a.z*a.z + a.w*a.w
                 + b.x*b.x + b.y*b.y + b.z*b.z + b.w*b.w;
        #pragma unroll
        for (int off = 16; off > 0; off >>= 1) {
            s  += __shfl_xor_sync(0xffffffffu, s,  off);
            sq += __shfl_xor_sync(0xffffffffu, sq, off);
        }
        const float mean = s * (1.0f / C_M);
        const float inv  = rsqrtf(sq * (1.0f / C_M) - mean * mean + EPS);

        const int c0 = lane * 4;
        const int c1 = (lane + 32) * 4;
        const float4 g0  = *reinterpret_cast<const float4*>(g_m  + c0);
        const float4 be0 = *reinterpret_cast<const float4*>(be_m + c0);
        const float4 g1  = *reinterpret_cast<const float4*>(g_m  + c1);
        const float4 be1 = *reinterpret_cast<const float4*>(be_m + c1);

        float4 oa, ob;
        oa.x = (a.x - mean) * inv * g0.x + be0.x;
        oa.y = (a.y - mean) * inv * g0.y + be0.y;
        oa.z = (a.z - mean) * inv * g0.z + be0.z;
        oa.w = (a.w - mean) * inv * g0.w + be0.w;
        ob.x = (b.x - mean) * inv * g1.x + be1.x;
        ob.y = (b.y - mean) * inv * g1.y + be1.y;
        ob.z = (b.z - mean) * inv * g1.z + be1.z;
        ob.w = (b.w - mean) * inv * g1.w + be1.w;

        float4* orow = reinterpret_cast<float4*>(out_m + (size_t)row * C_M);
        orow[lane]      = oa;
        orow[lane + 32] = ob;
        return;
    }

    // =====================================================================
    // z path: one warp per 16 consecutive (i,j) pairs (same i: 16 | 768).
    // =====================================================================
    __shared__ float ft_s[16 * C_Z];
    #pragma unroll
    for (int idx = threadIdx.x; idx < 16 * C_Z; idx += 256) {
        const int bin = idx >> 7;
        const int ch  = idx & 127;
        float v = b_lin[ch] + be_z[ch];
        if (bin < NO_BINS) v += w_lin[ch * NO_BINS + bin];
        ft_s[idx] = v;
    }
    __syncthreads();

    const unsigned warp = blockIdx.x * 8u + (threadIdx.x >> 5);
    const unsigned row_base = warp * ROWS_PER_WARP;
    const unsigned i = row_base / N_RES;
    const unsigned j = (row_base - i * N_RES) + (lane & 15u);  // lanes 16-31 dup

    // ---- Phase A: bin for pair (i, j); lane r holds bin of row r (r<16) ----
    const float dx = __ldg(&x[i * 3 + 0]) - __ldg(&x[j * 3 + 0]);
    const float dy = __ldg(&x[i * 3 + 1]) - __ldg(&x[j * 3 + 1]);
    const float dz = __ldg(&x[i * 3 + 2]) - __ldg(&x[j * 3 + 2]);
    const float d2 = dx * dx + dy * dy + dz * dz;

    int cnt = 0;
    cnt += (d2 > E0);  cnt += (d2 > E1);  cnt += (d2 > E2);  cnt += (d2 > E3);
    cnt += (d2 > E4);  cnt += (d2 > E5);  cnt += (d2 > E6);  cnt += (d2 > E7);
    cnt += (d2 > E8);  cnt += (d2 > E9);  cnt += (d2 > E10); cnt += (d2 > E11);
    cnt += (d2 > E12); cnt += (d2 > E13); cnt += (d2 > E14);
    const int mybin = (cnt == 0) ? 15 : (cnt - 1);

    // ---- per-warp invariants ----
    const float4 g = *reinterpret_cast<const float4*>(g_z + lane * 4);
    const float4* zb  = reinterpret_cast<const float4*>(z + (size_t)row_base * C_Z) + lane;
    float4*       obp = reinterpret_cast<float4*>(out_z + (size_t)row_base * C_Z) + lane;
    const float* ft = ft_s + lane * 4;

    // ---- Phase B: stream 16 rows, 2/iter, double-buffered ----
    float4 v0 = __ldcs(zb + 0 * 32);
    float4 v1 = __ldcs(zb + 1 * 32);

    #pragma unroll
    for (int r = 0; r < ROWS_PER_WARP; r += 2) {
        float4 n0, n1;
        if (r + 2 < ROWS_PER_WARP) {
            n0 = __ldcs(zb + (r + 2) * 32);
            n1 = __ldcs(zb + (r + 3) * 32);
        }

        float s0 = v0.x + v0.y + v0.z + v0.w;
        float q0 = v0.x*v0.x + v0.y*v0.y + v0.z*v0.z + v0.w*v0.w;
        float s1 = v1.x + v1.y + v1.z + v1.w;
        float q1 = v1.x*v1.x + v1.y*v1.y + v1.z*v1.z + v1.w*v1.w;

        #pragma unroll
        for (int off = 16; off > 0; off >>= 1) {
            s0 += __shfl_xor_sync(0xffffffffu, s0, off);
            q0 += __shfl_xor_sync(0xffffffffu, q0, off);
            s1 += __shfl_xor_sync(0xffffffffu, s1, off);
            q1 += __shfl_xor_sync(0xffffffffu, q1, off);
        }

        const float m0 = s0 * (1.0f / C_Z);
        const float i0 = rsqrtf(q0 * (1.0f / C_Z) - m0 * m0 + EPS);
        const float m1 = s1 * (1.0f / C_Z);
        const float i1 = rsqrtf(q1 * (1.0f / C_Z) - m1 * m1 + EPS);

        const int b0 = __shfl_sync(0xffffffffu, mybin, r + 0);
        const int b1 = __shfl_sync(0xffffffffu, mybin, r + 1);

        const float4 f0 = *reinterpret_cast<const float4*>(ft + b0 * C_Z);
        const float4 f1 = *reinterpret_cast<const float4*>(ft + b1 * C_Z);

        float4 o;
        o.x = f0.x + (v0.x - m0) * i0 * g.x;
        o.y = f0.y + (v0.y - m0) * i0 * g.y;
        o.z = f0.z + (v0.z - m0) * i0 * g.z;
        o.w = f0.w + (v0.w - m0) * i0 * g.w;
        __stcs(obp + (r + 0) * 32, o);
        o.x = f1.x + (v1.x - m1) * i1 * g.x;
        o.y = f1.y + (v1.y - m1) * i1 * g.y;
        o.z = f1.z + (v1.z - m1) * i1 * g.z;
        o.w = f1.w + (v1.w - m1) * i1 * g.w;
        __stcs(obp + (r + 1) * 32, o);

        v0 = n0; v1 = n1;
    }
}

// ---------------------------------------------------------------------------
// Inputs (metadata order): m, z, x, w_lin, b_lin, g_m, be_m, g_z, be_z
// Output: concat(flatten(m_update), flatten(z_update))
// ---------------------------------------------------------------------------
extern "C" void kernel_launch(void* const* d_in, const int* in_sizes, int n_in,
                              void* d_out, int out_size)
{
    const float* m     = (const float*)d_in[0];
    const float* z     = (const float*)d_in[1];
    const float* x     = (const float*)d_in[2];
    const float* w_lin = (const float*)d_in[3];
    const float* b_lin = (const float*)d_in[4];
    const float* g_m   = (const float*)d_in[5];
    const float* be_m  = (const float*)d_in[6];
    const float* g_z   = (const float*)d_in[7];
    const float* be_z  = (const float*)d_in[8];

    float* out_m = (float*)d_out;
    float* out_z = out_m + (size_t)N_RES * C_M;

    fused_kernel<<<NZBLOCKS + NMBLOCKS, 256>>>(
        z, x, g_z, m, g_m, be_m, w_lin, b_lin, be_z, out_m, out_z);
}

// round 14
// speedup vs baseline: 1.0072x; 1.0072x over previous
#include <cuda_runtime.h>
#include <cstdint>

#define N_RES 768
#define C_M   256
#define C_Z   128
#define NO_BINS 15
#define EPS 1e-5f

#define ROWS_PER_WARP 8
#define NZBLOCKS ((N_RES * N_RES) / ROWS_PER_WARP / 8)   // 9216
#define NMBLOCKS (N_RES / 8)                              // 96

// Squared bin edges (3.25 + 1.25k)^2 — exactly representable in fp32.
#define E0  10.5625f
#define E1  20.25f
#define E2  33.0625f
#define E3  49.0f
#define E4  68.0625f
#define E5  90.25f
#define E6  115.5625f
#define E7  144.0f
#define E8  175.5625f
#define E9  210.25f
#define E10 248.0625f
#define E11 289.0f
#define E12 333.0625f
#define E13 380.25f
#define E14 430.5625f

__global__ __launch_bounds__(256, 5)
void fused_kernel(const float* __restrict__ z,
                  const float* __restrict__ x,
                  const float* __restrict__ g_z,
                  const float* __restrict__ m,
                  const float* __restrict__ g_m,
                  const float* __restrict__ be_m,
                  const float* __restrict__ w_lin,   // [C_Z, NO_BINS]
                  const float* __restrict__ b_lin,   // [C_Z]
                  const float* __restrict__ be_z,    // [C_Z]
                  float* __restrict__ out_m,
                  float* __restrict__ out_z)
{
    const unsigned lane = threadIdx.x & 31u;

    // =====================================================================
    // m-layernorm path: blocks [NZBLOCKS, NZBLOCKS + NMBLOCKS)
    // =====================================================================
    if (blockIdx.x >= NZBLOCKS) {
        const unsigned row = (blockIdx.x - NZBLOCKS) * 8u + (threadIdx.x >> 5);

        const float4* mrow = reinterpret_cast<const float4*>(m + (size_t)row * C_M);
        float4 a = mrow[lane];
        float4 b = mrow[lane + 32];

        float s  = a.x + a.y + a.z + a.w + b.x + b.y + b.z + b.w;
        float sq = a.x*a.x + a.y*a.y + a.z*a.z + a.w*a.w
                 + b.x*b.x + b.y*b.y + b.z*b.z + b.w*b.w;
        #pragma unroll
        for (int off = 16; off > 0; off >>= 1) {
            s  += __shfl_xor_sync(0xffffffffu, s,  off);
            sq += __shfl_xor_sync(0xffffffffu, sq, off);
        }
        const float mean = s * (1.0f / C_M);
        const float inv  = rsqrtf(sq * (1.0f / C_M) - mean * mean + EPS);

        const int c0 = lane * 4;
        const int c1 = (lane + 32) * 4;
        const float4 g0  = *reinterpret_cast<const float4*>(g_m  + c0);
        const float4 be0 = *reinterpret_cast<const float4*>(be_m + c0);
        const float4 g1  = *reinterpret_cast<const float4*>(g_m  + c1);
        const float4 be1 = *reinterpret_cast<const float4*>(be_m + c1);

        float4 oa, ob;
        oa.x = (a.x - mean) * inv * g0.x + be0.x;
        oa.y = (a.y - mean) * inv * g0.y + be0.y;
        oa.z = (a.z - mean) * inv * g0.z + be0.z;
        oa.w = (a.w - mean) * inv * g0.w + be0.w;
        ob.x = (b.x - mean) * inv * g1.x + be1.x;
        ob.y = (b.y - mean) * inv * g1.y + be1.y;
        ob.z = (b.z - mean) * inv * g1.z + be1.z;
        ob.w = (b.w - mean) * inv * g1.w + be1.w;

        float4* orow = reinterpret_cast<float4*>(out_m + (size_t)row * C_M);
        orow[lane]      = oa;
        orow[lane + 32] = ob;
        return;
    }

    // =====================================================================
    // z path: one warp per 8 consecutive (i,j) pairs (same i: 8 | 768).
    // =====================================================================
    __shared__ float ft_s[16 * C_Z];
    #pragma unroll
    for (int idx = threadIdx.x; idx < 16 * C_Z; idx += 256) {
        const int bin = idx >> 7;
        const int ch  = idx & 127;
        float v = b_lin[ch] + be_z[ch];
        if (bin < NO_BINS) v += w_lin[ch * NO_BINS + bin];
        ft_s[idx] = v;
    }
    __syncthreads();

    const unsigned warp = blockIdx.x * 8u + (threadIdx.x >> 5);
    const unsigned row_base = warp * ROWS_PER_WARP;
    const unsigned i = row_base / N_RES;
    const unsigned j = (row_base - i * N_RES) + (lane & 7u);   // lanes 8-31 dup

    // ---- Phase A: bin for pair (i, j); lane r holds bin of row r (r<8) ----
    const float dx = __ldg(&x[i * 3 + 0]) - __ldg(&x[j * 3 + 0]);
    const float dy = __ldg(&x[i * 3 + 1]) - __ldg(&x[j * 3 + 1]);
    const float dz = __ldg(&x[i * 3 + 2]) - __ldg(&x[j * 3 + 2]);
    const float d2 = dx * dx + dy * dy + dz * dz;

    int cnt = 0;
    cnt += (d2 > E0);  cnt += (d2 > E1);  cnt += (d2 > E2);  cnt += (d2 > E3);
    cnt += (d2 > E4);  cnt += (d2 > E5);  cnt += (d2 > E6);  cnt += (d2 > E7);
    cnt += (d2 > E8);  cnt += (d2 > E9);  cnt += (d2 > E10); cnt += (d2 > E11);
    cnt += (d2 > E12); cnt += (d2 > E13); cnt += (d2 > E14);
    const int mybin = (cnt == 0) ? 15 : (cnt - 1);

    // ---- per-warp invariants ----
    const float4 g = *reinterpret_cast<const float4*>(g_z + lane * 4);
    const float4* zb  = reinterpret_cast<const float4*>(z + (size_t)row_base * C_Z) + lane;
    float4*       obp = reinterpret_cast<float4*>(out_z + (size_t)row_base * C_Z) + lane;
    const float* ft = ft_s + lane * 4;

    // ---- Phase B: stream 8 rows, 2/iter, double-buffered ----
    float4 v0 = __ldcs(zb + 0 * 32);
    float4 v1 = __ldcs(zb + 1 * 32);

    #pragma unroll
    for (int r = 0; r < ROWS_PER_WARP; r += 2) {
        float4 n0, n1;
        if (r + 2 < ROWS_PER_WARP) {
            n0 = __ldcs(zb + (r + 2) * 32);
            n1 = __ldcs(zb + (r + 3) * 32);
        }

        float s0 = v0.x + v0.y + v0.z + v0.w;
        float q0 = v0.x*v0.x + v0.y*v0.y + v0.z*v0.z + v0.w*v0.w;
        float s1 = v1.x + v1.y + v1.z + v1.w;
        float q1 = v1.x*v1.x + v1.y*v1.y + v1.z*v1.z + v1.w*v1.w;

        #pragma unroll
        for (int off = 16; off > 0; off >>= 1) {
            s0 += __shfl_xor_sync(0xffffffffu, s0, off);
            q0 += __shfl_xor_sync(0xffffffffu, q0, off);
            s1 += __shfl_xor_sync(0xffffffffu, s1, off);
            q1 += __shfl_xor_sync(0xffffffffu, q1, off);
        }

        const float m0 = s0 * (1.0f / C_Z);
        const float i0 = rsqrtf(q0 * (1.0f / C_Z) - m0 * m0 + EPS);
        const float m1 = s1 * (1.0f / C_Z);
        const float i1 = rsqrtf(q1 * (1.0f / C_Z) - m1 * m1 + EPS);

        const int b0 = __shfl_sync(0xffffffffu, mybin, r + 0);
        const int b1 = __shfl_sync(0xffffffffu, mybin, r + 1);

        const float4 f0 = *reinterpret_cast<const float4*>(ft + b0 * C_Z);
        const float4 f1 = *reinterpret_cast<const float4*>(ft + b1 * C_Z);

        float4 o;
        o.x = f0.x + (v0.x - m0) * i0 * g.x;
        o.y = f0.y + (v0.y - m0) * i0 * g.y;
        o.z = f0.z + (v0.z - m0) * i0 * g.z;
        o.w = f0.w + (v0.w - m0) * i0 * g.w;
        __stcs(obp + (r + 0) * 32, o);
        o.x = f1.x + (v1.x - m1) * i1 * g.x;
        o.y = f1.y + (v1.y - m1) * i1 * g.y;
        o.z = f1.z + (v1.z - m1) * i1 * g.z;
        o.w = f1.w + (v1.w - m1) * i1 * g.w;
        __stcs(obp + (r + 1) * 32, o);

        v0 = n0; v1 = n1;
    }
}

// ---------------------------------------------------------------------------
// Inputs (metadata order): m, z, x, w_lin, b_lin, g_m, be_m, g_z, be_z
// Output: concat(flatten(m_update), flatten(z_update))
// ---------------------------------------------------------------------------
extern "C" void kernel_launch(void* const* d_in, const int* in_sizes, int n_in,
                              void* d_out, int out_size)
{
    const float* m     = (const float*)d_in[0];
    const float* z     = (const float*)d_in[1];
    const float* x     = (const float*)d_in[2];
    const float* w_lin = (const float*)d_in[3];
    const float* b_lin = (const float*)d_in[4];
    const float* g_m   = (const float*)d_in[5];
    const float* be_m  = (const float*)d_in[6];
    const float* g_z   = (const float*)d_in[7];
    const float* be_z  = (const float*)d_in[8];

    float* out_m = (float*)d_out;
    float* out_z = out_m + (size_t)N_RES * C_M;

    fused_kernel<<<NZBLOCKS + NMBLOCKS, 256>>>(
        z, x, g_z, m, g_m, be_m, w_lin, b_lin, be_z, out_m, out_z);
}

// round 15
// speedup vs baseline: 1.0406x; 1.0332x over previous
#include <cuda_runtime.h>
#include <cstdint>

#define N_RES 768
#define C_M   256
#define C_Z   128
#define NO_BINS 15
#define EPS 1e-5f

#define ROWS_PER_WARP 4
#define NZBLOCKS ((N_RES * N_RES) / ROWS_PER_WARP / 8)   // 18432
#define NMBLOCKS (N_RES / 8)                              // 96

// Squared bin edges (3.25 + 1.25k)^2 — exactly representable in fp32.
#define E0  10.5625f
#define E1  20.25f
#define E2  33.0625f
#define E3  49.0f
#define E4  68.0625f
#define E5  90.25f
#define E6  115.5625f
#define E7  144.0f
#define E8  175.5625f
#define E9  210.25f
#define E10 248.0625f
#define E11 289.0f
#define E12 333.0625f
#define E13 380.25f
#define E14 430.5625f

__global__ __launch_bounds__(256, 5)
void fused_kernel(const float* __restrict__ z,
                  const float* __restrict__ x,
                  const float* __restrict__ g_z,
                  const float* __restrict__ m,
                  const float* __restrict__ g_m,
                  const float* __restrict__ be_m,
                  const float* __restrict__ w_lin,   // [C_Z, NO_BINS]
                  const float* __restrict__ b_lin,   // [C_Z]
                  const float* __restrict__ be_z,    // [C_Z]
                  float* __restrict__ out_m,
                  float* __restrict__ out_z)
{
    const unsigned lane = threadIdx.x & 31u;

    // =====================================================================
    // m-layernorm path: blocks [NZBLOCKS, NZBLOCKS + NMBLOCKS)
    // =====================================================================
    if (blockIdx.x >= NZBLOCKS) {
        const unsigned row = (blockIdx.x - NZBLOCKS) * 8u + (threadIdx.x >> 5);

        const float4* mrow = reinterpret_cast<const float4*>(m + (size_t)row * C_M);
        float4 a = mrow[lane];
        float4 b = mrow[lane + 32];

        float s  = a.x + a.y + a.z + a.w + b.x + b.y + b.z + b.w;
        float sq = a.x*a.x + a.y*a.y + a.z*a.z + a.w*a.w
                 + b.x*b.x + b.y*b.y + b.z*b.z + b.w*b.w;
        #pragma unroll
        for (int off = 16; off > 0; off >>= 1) {
            s  += __shfl_xor_sync(0xffffffffu, s,  off);
            sq += __shfl_xor_sync(0xffffffffu, sq, off);
        }
        const float mean = s * (1.0f / C_M);
        const float inv  = rsqrtf(sq * (1.0f / C_M) - mean * mean + EPS);

        const int c0 = lane * 4;
        const int c1 = (lane + 32) * 4;
        const float4 g0  = *reinterpret_cast<const float4*>(g_m  + c0);
        const float4 be0 = *reinterpret_cast<const float4*>(be_m + c0);
        const float4 g1  = *reinterpret_cast<const float4*>(g_m  + c1);
        const float4 be1 = *reinterpret_cast<const float4*>(be_m + c1);

        float4 oa, ob;
        oa.x = (a.x - mean) * inv * g0.x + be0.x;
        oa.y = (a.y - mean) * inv * g0.y + be0.y;
        oa.z = (a.z - mean) * inv * g0.z + be0.z;
        oa.w = (a.w - mean) * inv * g0.w + be0.w;
        ob.x = (b.x - mean) * inv * g1.x + be1.x;
        ob.y = (b.y - mean) * inv * g1.y + be1.y;
        ob.z = (b.z - mean) * inv * g1.z + be1.z;
        ob.w = (b.w - mean) * inv * g1.w + be1.w;

        float4* orow = reinterpret_cast<float4*>(out_m + (size_t)row * C_M);
        orow[lane]      = oa;
        orow[lane + 32] = ob;
        return;
    }

    // =====================================================================
    // z path: one warp per 4 consecutive (i,j) pairs (same i: 4 | 768).
    // =====================================================================
    __shared__ float ft_s[16 * C_Z];
    #pragma unroll
    for (int idx = threadIdx.x; idx < 16 * C_Z; idx += 256) {
        const int bin = idx >> 7;
        const int ch  = idx & 127;
        float v = b_lin[ch] + be_z[ch];
        if (bin < NO_BINS) v += w_lin[ch * NO_BINS + bin];
        ft_s[idx] = v;
    }
    __syncthreads();

    const unsigned warp = blockIdx.x * 8u + (threadIdx.x >> 5);
    const unsigned row_base = warp * ROWS_PER_WARP;
    const unsigned i = row_base / N_RES;
    const unsigned j = (row_base - i * N_RES) + (lane & 3u);   // lanes 4-31 dup

    // ---- Phase A: bin for pair (i, j); lane r holds bin of row r (r<4) ----
    const float dx = __ldg(&x[i * 3 + 0]) - __ldg(&x[j * 3 + 0]);
    const float dy = __ldg(&x[i * 3 + 1]) - __ldg(&x[j * 3 + 1]);
    const float dz = __ldg(&x[i * 3 + 2]) - __ldg(&x[j * 3 + 2]);
    const float d2 = dx * dx + dy * dy + dz * dz;

    int cnt = 0;
    cnt += (d2 > E0);  cnt += (d2 > E1);  cnt += (d2 > E2);  cnt += (d2 > E3);
    cnt += (d2 > E4);  cnt += (d2 > E5);  cnt += (d2 > E6);  cnt += (d2 > E7);
    cnt += (d2 > E8);  cnt += (d2 > E9);  cnt += (d2 > E10); cnt += (d2 > E11);
    cnt += (d2 > E12); cnt += (d2 > E13); cnt += (d2 > E14);
    const int mybin = (cnt == 0) ? 15 : (cnt - 1);

    // ---- per-warp invariants ----
    const float4 g = *reinterpret_cast<const float4*>(g_z + lane * 4);
    const float4* zb  = reinterpret_cast<const float4*>(z + (size_t)row_base * C_Z) + lane;
    float4*       obp = reinterpret_cast<float4*>(out_z + (size_t)row_base * C_Z) + lane;
    const float* ft = ft_s + lane * 4;

    // ---- Phase B: stream 4 rows, 2/iter, double-buffered ----
    float4 v0 = __ldcs(zb + 0 * 32);
    float4 v1 = __ldcs(zb + 1 * 32);

    #pragma unroll
    for (int r = 0; r < ROWS_PER_WARP; r += 2) {
        float4 n0, n1;
        if (r + 2 < ROWS_PER_WARP) {
            n0 = __ldcs(zb + (r + 2) * 32);
            n1 = __ldcs(zb + (r + 3) * 32);
        }

        float s0 = v0.x + v0.y + v0.z + v0.w;
        float q0 = v0.x*v0.x + v0.y*v0.y + v0.z*v0.z + v0.w*v0.w;
        float s1 = v1.x + v1.y + v1.z + v1.w;
        float q1 = v1.x*v1.x + v1.y*v1.y + v1.z*v1.z + v1.w*v1.w;

        #pragma unroll
        for (int off = 16; off > 0; off >>= 1) {
            s0 += __shfl_xor_sync(0xffffffffu, s0, off);
            q0 += __shfl_xor_sync(0xffffffffu, q0, off);
            s1 += __shfl_xor_sync(0xffffffffu, s1, off);
            q1 += __shfl_xor_sync(0xffffffffu, q1, off);
        }

        const float m0 = s0 * (1.0f / C_Z);
        const float i0 = rsqrtf(q0 * (1.0f / C_Z) - m0 * m0 + EPS);
        const float m1 = s1 * (1.0f / C_Z);
        const float i1 = rsqrtf(q1 * (1.0f / C_Z) - m1 * m1 + EPS);

        const int b0 = __shfl_sync(0xffffffffu, mybin, r + 0);
        const int b1 = __shfl_sync(0xffffffffu, mybin, r + 1);

        const float4 f0 = *reinterpret_cast<const float4*>(ft + b0 * C_Z);
        const float4 f1 = *reinterpret_cast<const float4*>(ft + b1 * C_Z);

        float4 o;
        o.x = f0.x + (v0.x - m0) * i0 * g.x;
        o.y = f0.y + (v0.y - m0) * i0 * g.y;
        o.z = f0.z + (v0.z - m0) * i0 * g.z;
        o.w = f0.w + (v0.w - m0) * i0 * g.w;
        __stcs(obp + (r + 0) * 32, o);
        o.x = f1.x + (v1.x - m1) * i1 * g.x;
        o.y = f1.y + (v1.y - m1) * i1 * g.y;
        o.z = f1.z + (v1.z - m1) * i1 * g.z;
        o.w = f1.w + (v1.w - m1) * i1 * g.w;
        __stcs(obp + (r + 1) * 32, o);

        v0 = n0; v1 = n1;
    }
}

// ---------------------------------------------------------------------------
// Inputs (metadata order): m, z, x, w_lin, b_lin, g_m, be_m, g_z, be_z
// Output: concat(flatten(m_update), flatten(z_update))
// ---------------------------------------------------------------------------
extern "C" void kernel_launch(void* const* d_in, const int* in_sizes, int n_in,
                              void* d_out, int out_size)
{
    const float* m     = (const float*)d_in[0];
    const float* z     = (const float*)d_in[1];
    const float* x     = (const float*)d_in[2];
    const float* w_lin = (const float*)d_in[3];
    const float* b_lin = (const float*)d_in[4];
    const float* g_m   = (const float*)d_in[5];
    const float* be_m  = (const float*)d_in[6];
    const float* g_z   = (const float*)d_in[7];
    const float* be_z  = (const float*)d_in[8];

    float* out_m = (float*)d_out;
    float* out_z = out_m + (size_t)N_RES * C_M;

    fused_kernel<<<NZBLOCKS + NMBLOCKS, 256>>>(
        z, x, g_z, m, g_m, be_m, w_lin, b_lin, be_z, out_m, out_z);
}